// round 11
// baseline (speedup 1.0000x reference)
#include <cuda_runtime.h>
#include <math.h>

#define BQ   1024
#define VN   6890
#define JN   24
#define NBT  10
#define PP   207
#define N3   20670     // VN*3
#define KE   224       // padded K: 207 pose_feature + 10 betas + 7 zeros
#define VPITCH 20736   // padded N (162*128)
#define NJOUT 61       // 24 + 11 + 9 + 17

// ---------------- device scratch (allocation-free) ----------------
__device__ float g_JST[JN * 33];
__device__ float g_pfe[BQ * KE];
__device__ float g_pde[KE * VPITCH];
__device__ float g_vposed[(size_t)BQ * VPITCH];
__device__ __align__(16) float g_A[BQ * JN * 12];

__constant__ int c_parents[24] = {-1,0,0,0,1,2,3,4,5,6,7,8,9,9,9,12,13,14,16,17,18,19,20,21};

// ---------------- K0a: fold J_regressor (792 blocks, coalesced) ----------------
__global__ void __launch_bounds__(256)
k0_fold(const float* __restrict__ Jreg,
        const float* __restrict__ shapedirs,
        const float* __restrict__ v_template) {
    int j = blockIdx.x / 33, o = blockIdx.x % 33;
    int k = o / 11, l = o % 11;
    int tid = threadIdx.x;
    float acc = 0.f;
    for (int v = tid; v < VN; v += 256) {
        float jr = Jreg[j * VN + v];
        float x  = (l < 10) ? shapedirs[v * 30 + k * 10 + l] : v_template[v * 3 + k];
        acc += jr * x;
    }
    __shared__ float red[256];
    red[tid] = acc;
    __syncthreads();
    #pragma unroll
    for (int s = 128; s >= 32; s >>= 1) {
        if (tid < s) red[tid] += red[tid + s];
        __syncthreads();
    }
    if (tid < 32) {
        float a = red[tid];
        #pragma unroll
        for (int s = 16; s; s >>= 1) a += __shfl_down_sync(0xffffffffu, a, s);
        if (tid == 0) g_JST[j * 33 + k * 11 + l] = a;
    }
}

// ---------------- K0b: build extended B matrix ----------------
__global__ void k0_pde(const float* __restrict__ posedirs,
                       const float* __restrict__ shapedirs) {
    int idx = blockIdx.x * blockDim.x + threadIdx.x;
    int row = idx / VPITCH;
    int col = idx - row * VPITCH;
    float val = 0.f;
    if (col < N3) {
        if (row < PP) {
            val = posedirs[row * N3 + col];
        } else if (row < PP + NBT) {
            int v = col / 3, k = col - v * 3, l = row - PP;
            val = shapedirs[v * 30 + k * 10 + l];
        }
    }
    g_pde[idx] = val;
}

// ---------------- K1: Rodrigues + Jrest + kinematic chain (1 warp/batch) ----------------
__global__ void k1_pose(const float* __restrict__ betas,
                        const float* __restrict__ poses,
                        float* __restrict__ out_joints) {
    int b = blockIdx.x;
    int lane = threadIdx.x;
    __shared__ float sh_b[NBT];
    __shared__ float sh_J[JN * 3];
    __shared__ float sh_T[JN * 12];
    __shared__ float sh_G[JN * 12];

    if (lane < NBT) sh_b[lane] = betas[b * NBT + lane];
    __syncthreads();

    float R[9];
    if (lane < JN) {
        int j = lane;
        float p0 = poses[b * 72 + j * 3 + 0];
        float p1 = poses[b * 72 + j * 3 + 1];
        float p2 = poses[b * 72 + j * 3 + 2];
        const float e = 1e-8f;
        float a0 = p0 + e, a1 = p1 + e, a2 = p2 + e;
        float ang = sqrtf(a0 * a0 + a1 * a1 + a2 * a2);
        float inv = 1.0f / ang;
        float rx = p0 * inv, ry = p1 * inv, rz = p2 * inv;
        float c = cosf(ang), s = sinf(ang), oc = 1.0f - c;
        R[0] = 1.f - oc * (ry * ry + rz * rz);
        R[1] = -s * rz + oc * rx * ry;
        R[2] =  s * ry + oc * rx * rz;
        R[3] =  s * rz + oc * rx * ry;
        R[4] = 1.f - oc * (rx * rx + rz * rz);
        R[5] = -s * rx + oc * ry * rz;
        R[6] = -s * ry + oc * rx * rz;
        R[7] =  s * rx + oc * ry * rz;
        R[8] = 1.f - oc * (rx * rx + ry * ry);

        if (j >= 1) {
            float* pf = &g_pfe[(size_t)b * KE + (j - 1) * 9];
            #pragma unroll
            for (int i = 0; i < 9; i++)
                pf[i] = R[i] - ((i == 0 || i == 4 || i == 8) ? 1.f : 0.f);
        }
        #pragma unroll
        for (int k = 0; k < 3; k++) {
            float acc = g_JST[j * 33 + k * 11 + 10];
            #pragma unroll
            for (int l = 0; l < NBT; l++) acc += sh_b[l] * g_JST[j * 33 + k * 11 + l];
            sh_J[j * 3 + k] = acc;
        }
    }
    if (lane < NBT)               g_pfe[(size_t)b * KE + PP + lane] = sh_b[lane];
    if (lane >= NBT && lane < 17) g_pfe[(size_t)b * KE + PP + lane] = 0.f;
    __syncthreads();

    if (lane < JN) {
        int j = lane;
        float r0 = sh_J[j * 3 + 0], r1 = sh_J[j * 3 + 1], r2 = sh_J[j * 3 + 2];
        if (j > 0) {
            int p = c_parents[j];
            r0 -= sh_J[p * 3 + 0]; r1 -= sh_J[p * 3 + 1]; r2 -= sh_J[p * 3 + 2];
        }
        sh_T[j*12+0]=R[0]; sh_T[j*12+1]=R[1]; sh_T[j*12+ 2]=R[2]; sh_T[j*12+ 3]=r0;
        sh_T[j*12+4]=R[3]; sh_T[j*12+5]=R[4]; sh_T[j*12+ 6]=R[5]; sh_T[j*12+ 7]=r1;
        sh_T[j*12+8]=R[6]; sh_T[j*12+9]=R[7]; sh_T[j*12+10]=R[8]; sh_T[j*12+11]=r2;
    }
    __syncthreads();

    if (lane < 12) sh_G[lane] = sh_T[lane];
    __syncthreads();
    for (int i = 1; i < JN; i++) {
        if (lane < 12) {
            int p = c_parents[i];
            int r = lane >> 2, cc = lane & 3;
            const float* Gp = &sh_G[p * 12 + r * 4];
            const float* Ti = &sh_T[i * 12];
            float v = Gp[0] * Ti[0 * 4 + cc] + Gp[1] * Ti[1 * 4 + cc] + Gp[2] * Ti[2 * 4 + cc];
            if (cc == 3) v += Gp[3];
            sh_G[i * 12 + lane] = v;
        }
        __syncthreads();
    }

    if (lane < JN) {
        int j = lane;
        const float* G = &sh_G[j * 12];
        float j0 = sh_J[j * 3 + 0], j1 = sh_J[j * 3 + 1], j2 = sh_J[j * 3 + 2];
        #pragma unroll
        for (int r = 0; r < 3; r++) {
            size_t base = ((size_t)b * JN + j) * 12 + (size_t)r * 4;
            float g0 = G[r*4+0], g1 = G[r*4+1], g2 = G[r*4+2], g3 = G[r*4+3];
            g_A[base + 0] = g0;
            g_A[base + 1] = g1;
            g_A[base + 2] = g2;
            g_A[base + 3] = g3 - (g0 * j0 + g1 * j1 + g2 * j2);
            out_joints[((size_t)b * NJOUT + j) * 3 + r] = g3;
        }
    }
}

// ---------------- tf32 helpers ----------------
__device__ __forceinline__ unsigned f2tf32(float f) {
    unsigned r;
    asm("cvt.rna.tf32.f32 %0, %1;" : "=r"(r) : "f"(f));
    return r;
}
__device__ __forceinline__ void mma_tf32(float* d, const unsigned* a, const unsigned* b) {
    asm("mma.sync.aligned.m16n8k8.row.col.f32.tf32.tf32.f32 "
        "{%0,%1,%2,%3}, {%4,%5,%6,%7}, {%8,%9}, {%0,%1,%2,%3};"
        : "+f"(d[0]), "+f"(d[1]), "+f"(d[2]), "+f"(d[3])
        : "r"(a[0]), "r"(a[1]), "r"(a[2]), "r"(a[3]), "r"(b[0]), "r"(b[1]));
}

// ---------------- K2: tf32 tensor-core GEMM 128x128x32 (known-good) ----------------
#define ASTRIDE 36
#define BSTRIDE 136

__global__ void __launch_bounds__(256)
k2_gemm(const float* __restrict__ v_template) {
    __shared__ unsigned As[128 * ASTRIDE];
    __shared__ unsigned Bs[32 * BSTRIDE];

    int tid  = threadIdx.x;
    int wid  = tid >> 5, lane = tid & 31;
    int gid  = lane >> 2, tig = lane & 3;
    int wm   = wid & 1;
    int wn   = wid >> 1;
    int m0   = blockIdx.y * 128;
    int n0   = blockIdx.x * 128;

    int aRow = tid >> 3, aCol = (tid & 7) * 4;
    int bRow = tid >> 5, bCol = (tid & 31) * 4;

    float acc[4][4][4];
    #pragma unroll
    for (int i = 0; i < 4; i++)
        #pragma unroll
        for (int j = 0; j < 4; j++)
            #pragma unroll
            for (int r = 0; r < 4; r++) acc[i][j][r] = 0.f;

    float4 ra[4], rb[4];
    #pragma unroll
    for (int i = 0; i < 4; i++) {
        ra[i] = *(const float4*)&g_pfe[(size_t)(m0 + aRow + i * 32) * KE + aCol];
        rb[i] = *(const float4*)&g_pde[(size_t)(bRow + i * 8) * VPITCH + n0 + bCol];
    }

    for (int kt = 0; kt < KE; kt += 32) {
        #pragma unroll
        for (int i = 0; i < 4; i++) {
            unsigned* pa = &As[(aRow + i * 32) * ASTRIDE + aCol];
            pa[0] = f2tf32(ra[i].x); pa[1] = f2tf32(ra[i].y);
            pa[2] = f2tf32(ra[i].z); pa[3] = f2tf32(ra[i].w);
            unsigned* pb = &Bs[(bRow + i * 8) * BSTRIDE + bCol];
            pb[0] = f2tf32(rb[i].x); pb[1] = f2tf32(rb[i].y);
            pb[2] = f2tf32(rb[i].z); pb[3] = f2tf32(rb[i].w);
        }
        __syncthreads();

        if (kt + 32 < KE) {
            #pragma unroll
            for (int i = 0; i < 4; i++) {
                ra[i] = *(const float4*)&g_pfe[(size_t)(m0 + aRow + i * 32) * KE + kt + 32 + aCol];
                rb[i] = *(const float4*)&g_pde[(size_t)(kt + 32 + bRow + i * 8) * VPITCH + n0 + bCol];
            }
        }

        #pragma unroll
        for (int ks = 0; ks < 4; ks++) {
            int k0 = ks * 8;
            unsigned af[4][4], bf[4][2];
            #pragma unroll
            for (int mt = 0; mt < 4; mt++) {
                int r = wm * 64 + mt * 16 + gid;
                af[mt][0] = As[(r)     * ASTRIDE + k0 + tig];
                af[mt][1] = As[(r + 8) * ASTRIDE + k0 + tig];
                af[mt][2] = As[(r)     * ASTRIDE + k0 + tig + 4];
                af[mt][3] = As[(r + 8) * ASTRIDE + k0 + tig + 4];
            }
            #pragma unroll
            for (int nt = 0; nt < 4; nt++) {
                int n = wn * 32 + nt * 8 + gid;
                bf[nt][0] = Bs[(k0 + tig)     * BSTRIDE + n];
                bf[nt][1] = Bs[(k0 + tig + 4) * BSTRIDE + n];
            }
            #pragma unroll
            for (int mt = 0; mt < 4; mt++)
                #pragma unroll
                for (int nt = 0; nt < 4; nt++)
                    mma_tf32(acc[mt][nt], af[mt], bf[nt]);
        }
        __syncthreads();
    }

    #pragma unroll
    for (int mt = 0; mt < 4; mt++) {
        int m = m0 + wm * 64 + mt * 16 + gid;
        #pragma unroll
        for (int nt = 0; nt < 4; nt++) {
            int n = n0 + wn * 32 + nt * 8 + 2 * tig;
            float b0v = (n     < N3) ? v_template[n]     : 0.f;
            float b1v = (n + 1 < N3) ? v_template[n + 1] : 0.f;
            float2 lo = make_float2(acc[mt][nt][0] + b0v, acc[mt][nt][1] + b1v);
            float2 hi = make_float2(acc[mt][nt][2] + b0v, acc[mt][nt][3] + b1v);
            *(float2*)&g_vposed[(size_t)m       * VPITCH + n] = lo;
            *(float2*)&g_vposed[(size_t)(m + 8) * VPITCH + n] = hi;
        }
    }
}

// ---------------- K3: skinning via 3xTF32 tensor-core GEMM ----------------
// Per block: 128-vertex tile x 8 batches. T(128x12) = W(128x24) @ A_b(24x12),
// applied immediately to v_posed. 3xTF32 (hi/lo split) => fp32-grade accuracy.
#define K3B  8
#define WSTR 25    // sW fp32 row stride (conflict-light for scalar frag loads)
#define ASTR 13    // sA fp32 row stride
#define TSTR 20    // sT row stride (conflict-free LDS.128 by 16 lanes)

__global__ void __launch_bounds__(256)
k3_skin(const float* __restrict__ lbs_weights,
        float* __restrict__ out_verts) {
    __shared__ float sW[128 * WSTR];               // 12.5 KB
    __shared__ float sA[K3B * JN * ASTR];          // 10.0 KB
    __shared__ float sT[8 * 16 * TSTR];            // 10.0 KB

    int tid = threadIdx.x;
    int wid = tid >> 5, lane = tid & 31;
    int gid = lane >> 2, tig = lane & 3;
    int v0 = blockIdx.x * 128;
    int b0 = blockIdx.y * K3B;

    // stage W tile (fp32), coalesced
    for (int i = tid; i < 128 * JN; i += 256) {
        int v = i / JN, j = i - v * JN;
        float val = (v0 + v < VN) ? lbs_weights[(size_t)(v0 + v) * JN + j] : 0.f;
        sW[v * WSTR + j] = val;
    }
    // stage A for 8 batches (fp32), coalesced
    for (int i = tid; i < K3B * 288; i += 256) {
        int bb = i / 288, r = i - bb * 288;
        int j = r / 12, e = r - j * 12;
        sA[(bb * JN + j) * ASTR + e] = g_A[(size_t)(b0 + bb) * 288 + r];
    }
    __syncthreads();

    // per-warp W fragments, hi/lo split (computed once)
    unsigned afh[3][4], afl[3][4];
    {
        const float* wb = &sW[(wid * 16) * WSTR];
        #pragma unroll
        for (int kk = 0; kk < 3; kk++) {
            int k0 = kk * 8;
            float f[4];
            f[0] = wb[(gid)     * WSTR + k0 + tig];
            f[1] = wb[(gid + 8) * WSTR + k0 + tig];
            f[2] = wb[(gid)     * WSTR + k0 + tig + 4];
            f[3] = wb[(gid + 8) * WSTR + k0 + tig + 4];
            #pragma unroll
            for (int q = 0; q < 4; q++) {
                unsigned h = f2tf32(f[q]);
                afh[kk][q] = h;
                afl[kk][q] = f2tf32(f[q] - __uint_as_float(h));
            }
        }
    }

    float* tw = &sT[wid * 16 * TSTR];

    for (int bb = 0; bb < K3B; bb++) {
        const float* ab = &sA[bb * JN * ASTR];
        float acc[2][4];
        #pragma unroll
        for (int nt = 0; nt < 2; nt++)
            #pragma unroll
            for (int q = 0; q < 4; q++) acc[nt][q] = 0.f;

        #pragma unroll
        for (int kk = 0; kk < 3; kk++) {
            int k0 = kk * 8;
            #pragma unroll
            for (int nt = 0; nt < 2; nt++) {
                int n = nt * 8 + gid;    // n: 0..15; cols >= 12 read pad (harmless)
                float f0 = (n < 12) ? ab[(k0 + tig)     * ASTR + n] : 0.f;
                float f1 = (n < 12) ? ab[(k0 + tig + 4) * ASTR + n] : 0.f;
                unsigned bh[2], bl[2];
                bh[0] = f2tf32(f0); bl[0] = f2tf32(f0 - __uint_as_float(bh[0]));
                bh[1] = f2tf32(f1); bl[1] = f2tf32(f1 - __uint_as_float(bh[1]));
                mma_tf32(acc[nt], afh[kk], bh);   // hi*hi
                unsigned bhh[2] = {bh[0], bh[1]};
                mma_tf32(acc[nt], afl[kk], bhh);  // lo*hi
                mma_tf32(acc[nt], afh[kk], bl);   // hi*lo
            }
        }

        // scatter T tile to smem (rows gid,gid+8; cols nt*8+2tig,+1)
        #pragma unroll
        for (int nt = 0; nt < 2; nt++) {
            int c = nt * 8 + 2 * tig;
            *(float2*)&tw[(gid)     * TSTR + c] = make_float2(acc[nt][0], acc[nt][1]);
            *(float2*)&tw[(gid + 8) * TSTR + c] = make_float2(acc[nt][2], acc[nt][3]);
        }
        __syncwarp();

        if (lane < 16) {
            int v = v0 + wid * 16 + lane;
            if (v < VN) {
                const float* t = &tw[lane * TSTR];
                float4 t0 = *(const float4*)&t[0];
                float4 t1 = *(const float4*)&t[4];
                float4 t2 = *(const float4*)&t[8];
                int b = b0 + bb;
                size_t vb = (size_t)b * VPITCH + (size_t)v * 3;
                float vx = g_vposed[vb + 0], vy = g_vposed[vb + 1], vz = g_vposed[vb + 2];
                float ox = t0.x * vx + t0.y * vy + t0.z * vz + t0.w;
                float oy = t1.x * vx + t1.y * vy + t1.z * vz + t1.w;
                float oz = t2.x * vx + t2.y * vy + t2.z * vz + t2.w;
                size_t ob = ((size_t)b * VN + v) * 3;
                out_verts[ob + 0] = ox;
                out_verts[ob + 1] = oy;
                out_verts[ob + 2] = oz;
            }
        }
        __syncwarp();
    }
}

// ---------------- K4: joint regression with smem-tiled regressor (R10 known-good) ----------------
#define K4B 4
#define CH  256
#define CHP 257
__global__ void __launch_bounds__(256)
k4_reg(const float* __restrict__ Je9,
       const float* __restrict__ Jh17,
       const float* __restrict__ verts,
       float* __restrict__ out_joints) {
    __shared__ float sJr[26 * CHP];
    __shared__ float sv[K4B][CH * 3];
    __shared__ float red[K4B][240];
    int b0 = blockIdx.x * K4B;
    int tid = threadIdx.x;

    int p = tid / 3;
    int s = tid - p * 3;
    int jj = p / 3, k = p - jj * 3;

    float acc[K4B];
    #pragma unroll
    for (int bb = 0; bb < K4B; bb++) acc[bb] = 0.f;

    for (int v0 = 0; v0 < VN; v0 += CH) {
        int cnt = VN - v0; if (cnt > CH) cnt = CH;
        for (int i = tid; i < 26 * cnt; i += 256) {
            int rj = i / cnt;
            int v  = i - rj * cnt;
            float val = (rj < 9) ? Je9[(size_t)rj * VN + v0 + v]
                                 : Jh17[(size_t)(rj - 9) * VN + v0 + v];
            sJr[rj * CHP + v] = val;
        }
        int n2 = (cnt * 3) / 2;
        #pragma unroll
        for (int bb = 0; bb < K4B; bb++) {
            const float* src = &verts[((size_t)(b0 + bb) * VN + v0) * 3];
            float2* dst2 = (float2*)&sv[bb][0];
            const float2* src2 = (const float2*)src;
            for (int i = tid; i < n2; i += 256)
                dst2[i] = src2[i];
            for (int i = n2 * 2 + tid; i < cnt * 3; i += 256)
                sv[bb][i] = src[i];
        }
        __syncthreads();
        if (tid < 234) {
            for (int v = s; v < cnt; v += 3) {
                float jr = sJr[jj * CHP + v];
                #pragma unroll
                for (int bb = 0; bb < K4B; bb++)
                    acc[bb] += jr * sv[bb][v * 3 + k];
            }
        }
        __syncthreads();
    }
    if (tid < 234) {
        #pragma unroll
        for (int bb = 0; bb < K4B; bb++) red[bb][tid] = acc[bb];
    }
    __syncthreads();
    if (tid < 78) {
        int jjo = tid / 3, ko = tid - jjo * 3;
        #pragma unroll
        for (int bb = 0; bb < K4B; bb++) {
            float total = red[bb][tid * 3] + red[bb][tid * 3 + 1] + red[bb][tid * 3 + 2];
            out_joints[((size_t)(b0 + bb) * NJOUT + 35 + jjo) * 3 + ko] = total;
        }
    }
}

// ---------------- K5: extra11 gather ----------------
__global__ void k5_gather(const int* __restrict__ idxs,
                          const float* __restrict__ verts,
                          float* __restrict__ out_joints) {
    int t = blockIdx.x * blockDim.x + threadIdx.x;
    int b = t / 33;
    int r = t - b * 33;
    int i = r / 3, k = r % 3;
    int v = idxs[i];
    out_joints[((size_t)b * NJOUT + 24 + i) * 3 + k] = verts[((size_t)b * VN + v) * 3 + k];
}

// ---------------- launch ----------------
extern "C" void kernel_launch(void* const* d_in, const int* in_sizes, int n_in,
                              void* d_out, int out_size) {
    (void)in_sizes; (void)n_in; (void)out_size;
    const float* betas      = (const float*)d_in[0];
    const float* poses      = (const float*)d_in[1];
    const int*   ext_idx    = (const int*)  d_in[2];
    const float* v_template = (const float*)d_in[3];
    const float* shapedirs  = (const float*)d_in[4];
    const float* posedirs   = (const float*)d_in[5];
    const float* Jreg       = (const float*)d_in[6];
    const float* lbs_w      = (const float*)d_in[7];
    const float* Je9        = (const float*)d_in[8];
    const float* Jh17       = (const float*)d_in[9];

    float* out_verts  = (float*)d_out;
    float* out_joints = out_verts + (size_t)BQ * VN * 3;

    k0_fold<<<JN * 33, 256>>>(Jreg, shapedirs, v_template);
    k0_pde<<<(KE * VPITCH) / 256, 256>>>(posedirs, shapedirs);
    k1_pose<<<BQ, 32>>>(betas, poses, out_joints);
    k2_gemm<<<dim3(VPITCH / 128, BQ / 128), 256>>>(v_template);
    k3_skin<<<dim3((VN + 127) / 128, BQ / K3B), 256>>>(lbs_w, out_verts);
    k4_reg<<<BQ / K4B, 256>>>(Je9, Jh17, out_verts, out_joints);
    k5_gather<<<(BQ * 11 * 3) / 256, 256>>>(ext_idx, out_verts, out_joints);
}